// round 5
// baseline (speedup 1.0000x reference)
#include <cuda_runtime.h>
#include <cuda_bf16.h>

#define BATCH 64
#define FDIM 768     // 3 * 16 * 16
#define DDIM 128
#define KCLS 1000

// Scratch (no allocations allowed in kernel_launch)
__device__ float g_scratch[BATCH * FDIM];     // per-batch global-mean patch vector
__device__ float root_scratch[BATCH * DDIM];  // root token per batch

// ---------------------------------------------------------------------------
// K1: g[b, c*256 + pi*16 + pj] = (1/256) * sum_{h,w} x[b,c,16h+pi,16w+pj]
// One block per (b,c,pi) = 64*3*16 = 3072 blocks, 256 threads (one per column).
// ---------------------------------------------------------------------------
__global__ void reduce_patches_kernel(const float* __restrict__ x) {
    int blk = blockIdx.x;            // b*48 + c*16 + pi
    int b   = blk / 48;
    int rem = blk % 48;
    int c   = rem >> 4;
    int pi  = rem & 15;
    int t   = threadIdx.x;           // column index 0..255 (co = 16*w + pj)

    const float* base = x + (((size_t)(b * 3 + c) * 256 + pi) * 256);

    float acc = 0.0f;
    #pragma unroll
    for (int h = 0; h < 16; ++h)
        acc += base[h * 16 * 256 + t];   // rows 16h+pi, fully coalesced

    __shared__ float s[256];
    s[t] = acc;
    __syncthreads();

    if (t < 16) {                    // t == pj
        float sum = 0.0f;
        #pragma unroll
        for (int w = 0; w < 16; ++w)
            sum += s[w * 16 + t];    // consecutive addresses across lanes: no conflicts
        g_scratch[b * FDIM + c * 256 + pi * 16 + t] = sum * (1.0f / 256.0f);
    }
}

// ---------------------------------------------------------------------------
// K2: root[b,d] = dot(W_emb[d,:], g[b,:]) + b_emb[d] + pos4[d]
// One block per b, 128 threads (one per d). g[b] staged in shared (broadcast).
// ---------------------------------------------------------------------------
__global__ void embed_root_kernel(const float* __restrict__ W_emb,
                                  const float* __restrict__ b_emb,
                                  const float* __restrict__ pos4) {
    int b = blockIdx.x;
    int d = threadIdx.x;             // 0..127

    __shared__ __align__(16) float g_sh[FDIM];
    #pragma unroll
    for (int i = d; i < FDIM; i += DDIM)
        g_sh[i] = g_scratch[b * FDIM + i];
    __syncthreads();

    const float4* w4 = reinterpret_cast<const float4*>(W_emb + (size_t)d * FDIM);
    const float4* g4 = reinterpret_cast<const float4*>(g_sh);

    float acc = 0.0f;
    #pragma unroll 8
    for (int i = 0; i < FDIM / 4; ++i) {
        float4 w = w4[i];
        float4 g = g4[i];            // broadcast across all lanes per i
        acc += w.x * g.x + w.y * g.y + w.z * g.z + w.w * g.w;
    }
    root_scratch[b * DDIM + d] = acc + b_emb[d] + pos4[d];
}

// ---------------------------------------------------------------------------
// K3: logits[b,k] = dot(W_cls[k,:], root[b,:]) + b_cls[k]
// One block per b, 256 threads; each thread handles ~4 classes.
// ---------------------------------------------------------------------------
__global__ void classify_kernel(const float* __restrict__ W_cls,
                                const float* __restrict__ b_cls,
                                float* __restrict__ out) {
    int b = blockIdx.x;
    int t = threadIdx.x;             // 0..255

    __shared__ __align__(16) float r_sh[DDIM];
    if (t < DDIM) r_sh[t] = root_scratch[b * DDIM + t];
    __syncthreads();

    const float4* r4 = reinterpret_cast<const float4*>(r_sh);
    for (int k = t; k < KCLS; k += 256) {
        const float4* w4 = reinterpret_cast<const float4*>(W_cls + (size_t)k * DDIM);
        float acc = 0.0f;
        #pragma unroll
        for (int i = 0; i < DDIM / 4; ++i) {
            float4 w = w4[i];
            float4 r = r4[i];
            acc += w.x * r.x + w.y * r.y + w.z * r.z + w.w * r.w;
        }
        out[b * KCLS + k] = acc + b_cls[k];
    }
}

// ---------------------------------------------------------------------------
// Inputs (metadata order):
//   0: x (64,3,256,256)   1: W_emb (128,768)   2: b_emb (128)
//   3..7: pos0..pos4      8: W_cls (1000,128)  9: b_cls (1000)
// Output: logits (64,1000) float32
// Only x, W_emb, b_emb, pos4, W_cls, b_cls are live (levels 0-3 and pos0-3
// are dead code in the reference: output uses only the global-mean level).
// ---------------------------------------------------------------------------
extern "C" void kernel_launch(void* const* d_in, const int* in_sizes, int n_in,
                              void* d_out, int out_size) {
    const float* x     = (const float*)d_in[0];
    const float* W_emb = (const float*)d_in[1];
    const float* b_emb = (const float*)d_in[2];
    const float* pos4  = (const float*)d_in[7];
    const float* W_cls = (const float*)d_in[8];
    const float* b_cls = (const float*)d_in[9];
    float* out = (float*)d_out;

    reduce_patches_kernel<<<BATCH * 48, 256>>>(x);
    embed_root_kernel<<<BATCH, DDIM>>>(W_emb, b_emb, pos4);
    classify_kernel<<<BATCH, 256>>>(W_cls, b_cls, out);
}

// round 6
// speedup vs baseline: 2.3391x; 2.3391x over previous
#include <cuda_runtime.h>
#include <cuda_bf16.h>

#define BATCH 64
#define FDIM 768     // 3 * 16 * 16
#define DDIM 128
#define KCLS 1000

// Scratch (no allocations allowed in kernel_launch)
__device__ float g_scratch[BATCH * FDIM];     // per-batch global-mean patch vector
__device__ float root_scratch[BATCH * DDIM];  // root token per batch

// ---------------------------------------------------------------------------
// K1: g[b, c*256 + pi*16 + pj] = (1/256) * sum_{h,w} x[b,c,16h+pi,16w+pj]
// Block = (b, c, pi-group of 4): 64*3*4 = 768 blocks, 256 threads.
// Thread (pi_local = t/64, col4 = t%64) accumulates a float4 over 16 rows:
// 16 outstanding LDG.128 per thread, warp requests are 512B contiguous.
// ---------------------------------------------------------------------------
__global__ void reduce_patches_kernel(const float* __restrict__ x) {
    int blk = blockIdx.x;            // b*12 + c*4 + pig
    int b   = blk / 12;
    int rem = blk % 12;
    int c   = rem >> 2;
    int pig = rem & 3;
    int t   = threadIdx.x;
    int pi_l = t >> 6;               // 0..3
    int col4 = t & 63;               // float4 column index 0..63
    int pi  = pig * 4 + pi_l;

    const float4* base = reinterpret_cast<const float4*>(
        x + (((size_t)(b * 3 + c) * 256 + pi) * 256));

    float4 acc = make_float4(0.f, 0.f, 0.f, 0.f);
    #pragma unroll
    for (int h = 0; h < 16; ++h) {
        float4 v = base[h * 16 * 64 + col4];   // row 16h+pi
        acc.x += v.x; acc.y += v.y; acc.z += v.z; acc.w += v.w;
    }

    __shared__ float4 s[4][64];
    s[pi_l][col4] = acc;
    __syncthreads();

    // 64 reducer threads: (pi_l2 = t/16, pj = t%16); sum over w of col 16w+pj
    if (t < 64) {
        int pl = t >> 4;
        int pj = t & 15;
        const float* sf = reinterpret_cast<const float*>(s[pl]);
        float sum = 0.0f;
        #pragma unroll
        for (int w = 0; w < 16; ++w)
            sum += sf[16 * w + pj];
        int piw = pig * 4 + pl;
        g_scratch[b * FDIM + c * 256 + piw * 16 + pj] = sum * (1.0f / 256.0f);
    }
}

// ---------------------------------------------------------------------------
// K2: root[b,d] = dot(W_emb[d,:], g[b,:]) + b_emb[d] + pos4[d]
// Grid: (128 d, 2 b-halves) = 256 blocks, 256 threads = 32 b x 8 segments.
// W row in shared; g loads: fixed i -> per-b 8 consecutive float4 (128B).
// ---------------------------------------------------------------------------
__global__ void embed_root_kernel(const float* __restrict__ W_emb,
                                  const float* __restrict__ b_emb,
                                  const float* __restrict__ pos4) {
    int d    = blockIdx.x;           // 0..127
    int half = blockIdx.y;           // 0..1
    int t    = threadIdx.x;
    int b    = half * 32 + (t >> 3);
    int seg  = t & 7;

    __shared__ __align__(16) float w_sh[FDIM];
    for (int i = t; i < FDIM; i += 256)
        w_sh[i] = W_emb[(size_t)d * FDIM + i];
    __syncthreads();

    const float4* g4 = reinterpret_cast<const float4*>(g_scratch + (size_t)b * FDIM);
    const float4* w4 = reinterpret_cast<const float4*>(w_sh);

    float acc = 0.0f;
    #pragma unroll
    for (int i = 0; i < 24; ++i) {
        int f4 = i * 8 + seg;
        float4 g = g4[f4];
        float4 w = w4[f4];
        acc += w.x * g.x + w.y * g.y + w.z * g.z + w.w * g.w;
    }
    // reduce across the 8 segment lanes (aligned 8-groups within warp)
    acc += __shfl_xor_sync(0xFFFFFFFFu, acc, 1);
    acc += __shfl_xor_sync(0xFFFFFFFFu, acc, 2);
    acc += __shfl_xor_sync(0xFFFFFFFFu, acc, 4);

    if (seg == 0)
        root_scratch[b * DDIM + d] = acc + b_emb[d] + pos4[d];
}

// ---------------------------------------------------------------------------
// K3: logits[b,k] = dot(W_cls[k,:], root[b,:]) + b_cls[k]
// Grid: 250 blocks (4 classes each), 256 threads = 64 b x 4 k.
// All 64 roots + 4 W_cls rows staged in shared (rows padded to 132 floats
// -> conflict-free LDS.128). Each thread does one dot-128 from shared.
// ---------------------------------------------------------------------------
#define RPAD 132

__global__ void classify_kernel(const float* __restrict__ W_cls,
                                const float* __restrict__ b_cls,
                                float* __restrict__ out) {
    int kbase = blockIdx.x * 4;
    int t = threadIdx.x;

    __shared__ __align__(16) float r_sh[BATCH * RPAD];  // 33792 B
    __shared__ __align__(16) float w_sh[4 * RPAD];      //  2112 B

    // load roots: 2048 float4s (132*4B = 528B row stride, 16B-aligned)
    {
        const float4* src = reinterpret_cast<const float4*>(root_scratch);
        for (int idx = t; idx < BATCH * (DDIM / 4); idx += 256) {
            int b  = idx >> 5;        // /32
            int i4 = idx & 31;
            *reinterpret_cast<float4*>(&r_sh[b * RPAD + i4 * 4]) = src[idx];
        }
    }
    // load 4 W_cls rows
    {
        const float4* src = reinterpret_cast<const float4*>(W_cls + (size_t)kbase * DDIM);
        for (int idx = t; idx < 4 * (DDIM / 4); idx += 256) {
            int k  = idx >> 5;
            int i4 = idx & 31;
            *reinterpret_cast<float4*>(&w_sh[k * RPAD + i4 * 4]) = src[idx];
        }
    }
    __syncthreads();

    int b = t >> 2;
    int k = t & 3;
    const float4* r4 = reinterpret_cast<const float4*>(&r_sh[b * RPAD]);
    const float4* w4 = reinterpret_cast<const float4*>(&w_sh[k * RPAD]);

    float acc = 0.0f;
    #pragma unroll
    for (int i = 0; i < DDIM / 4; ++i) {
        float4 w = w4[i];
        float4 r = r4[i];
        acc += w.x * r.x + w.y * r.y + w.z * r.z + w.w * r.w;
    }
    out[b * KCLS + kbase + k] = acc + b_cls[kbase + k];
}

// ---------------------------------------------------------------------------
// Inputs (metadata order):
//   0: x (64,3,256,256)   1: W_emb (128,768)   2: b_emb (128)
//   3..7: pos0..pos4      8: W_cls (1000,128)  9: b_cls (1000)
// Output: logits (64,1000) float32
// Only x, W_emb, b_emb, pos4, W_cls, b_cls are live (levels 0-3 and pos0-3
// are dead code in the reference: output uses only the global-mean level).
// ---------------------------------------------------------------------------
extern "C" void kernel_launch(void* const* d_in, const int* in_sizes, int n_in,
                              void* d_out, int out_size) {
    const float* x     = (const float*)d_in[0];
    const float* W_emb = (const float*)d_in[1];
    const float* b_emb = (const float*)d_in[2];
    const float* pos4  = (const float*)d_in[7];
    const float* W_cls = (const float*)d_in[8];
    const float* b_cls = (const float*)d_in[9];
    float* out = (float*)d_out;

    reduce_patches_kernel<<<BATCH * 12, 256>>>(x);
    embed_root_kernel<<<dim3(DDIM, 2), 256>>>(W_emb, b_emb, pos4);
    classify_kernel<<<KCLS / 4, 256>>>(W_cls, b_cls, out);
}